// round 6
// baseline (speedup 1.0000x reference)
#include <cuda_runtime.h>
#include <cuda_bf16.h>
#include <math.h>
#include <stdint.h>

#define NLAYERS 12
#define D 256
#define H 8
#define DK 32
#define FFD 1024
#define BATCH 32
#define SEQ 448
#define NTOK (BATCH*SEQ)   /* 14336 */

// ---------------- scratch (no allocations allowed) ----------------
__device__ float g_qkv[NTOK * 768];
__device__ __nv_bfloat16 g_nxh[NTOK * D], g_nxl[NTOK * D];
__device__ __nv_bfloat16 g_aoh[NTOK * D], g_aol[NTOK * D];
__device__ __nv_bfloat16 g_hh [NTOK * FFD], g_hl [NTOK * FFD];
// transposed + split weights
__device__ __nv_bfloat16 g_wqkvh[NLAYERS * 768 * D], g_wqkvl[NLAYERS * 768 * D];
__device__ __nv_bfloat16 g_woth [NLAYERS * D * D],   g_wotl [NLAYERS * D * D];
__device__ __nv_bfloat16 g_w1th [NLAYERS * FFD * D], g_w1tl [NLAYERS * FFD * D];
__device__ __nv_bfloat16 g_w2th [NLAYERS * D * FFD], g_w2tl [NLAYERS * D * FFD];

// ---------------- helpers ----------------
__device__ __forceinline__ uint32_t smem_u32(const void* p) {
    uint32_t a;
    asm("{ .reg .u64 t; cvta.to.shared.u64 t, %1; cvt.u32.u64 %0, t; }" : "=r"(a) : "l"(p));
    return a;
}
__device__ __forceinline__ void cp16(uint32_t dst, const void* src) {
    asm volatile("cp.async.ca.shared.global [%0], [%1], 16;" :: "r"(dst), "l"(src));
}
#define CP_COMMIT() asm volatile("cp.async.commit_group;" ::: "memory")
#define CP_WAIT1()  asm volatile("cp.async.wait_group 1;" ::: "memory")

__device__ __forceinline__ void ldsm4(uint32_t* r, uint32_t addr) {
    asm volatile("ldmatrix.sync.aligned.m8n8.x4.shared.b16 {%0,%1,%2,%3}, [%4];"
        : "=r"(r[0]), "=r"(r[1]), "=r"(r[2]), "=r"(r[3]) : "r"(addr));
}
__device__ __forceinline__ void mma_bf16(float* d, const uint32_t* a, const uint32_t* b) {
    asm volatile(
        "mma.sync.aligned.m16n8k16.row.col.f32.bf16.bf16.f32 "
        "{%0,%1,%2,%3}, {%4,%5,%6,%7}, {%8,%9}, {%0,%1,%2,%3};"
        : "+f"(d[0]), "+f"(d[1]), "+f"(d[2]), "+f"(d[3])
        : "r"(a[0]), "r"(a[1]), "r"(a[2]), "r"(a[3]), "r"(b[0]), "r"(b[1]));
}
__device__ __forceinline__ void split2(float v, __nv_bfloat16& h, __nv_bfloat16& l) {
    h = __float2bfloat16(v);
    l = __float2bfloat16(v - __bfloat162float(h));
}
__device__ __forceinline__ float gelu_exact(float x) {
    return 0.5f * x * (1.0f + erff(x * 0.7071067811865475f));
}

// ---------------- pos-emb add ----------------
__global__ void add_pos_kernel(const float* __restrict__ xin,
                               const float* __restrict__ pos,
                               float* __restrict__ xout) {
    int idx = blockIdx.x * blockDim.x + threadIdx.x;
    int row = idx >> 6;
    int c4  = idx & 63;
    int l   = row % SEQ;
    float4 xv = ((const float4*)xin)[idx];
    float4 pv = ((const float4*)pos)[l * 64 + c4];
    xv.x += pv.x; xv.y += pv.y; xv.z += pv.z; xv.w += pv.w;
    ((float4*)xout)[idx] = xv;
}

// ---------------- weight transpose + hi/lo split ----------------
__global__ void wsplit_kernel(const float* __restrict__ W,
                              __nv_bfloat16* __restrict__ dh,
                              __nv_bfloat16* __restrict__ dl,
                              int K, int N, size_t dstLS) {
    __shared__ float t[32][33];
    int z = blockIdx.z;
    int nt = blockIdx.x * 32, kt = blockIdx.y * 32;
    const float* src = W + (size_t)z * K * N;
    #pragma unroll
    for (int i = 0; i < 32; i += 8)
        t[threadIdx.y + i][threadIdx.x] = src[(size_t)(kt + threadIdx.y + i) * N + nt + threadIdx.x];
    __syncthreads();
    __nv_bfloat16* dhp = dh + (size_t)z * dstLS;
    __nv_bfloat16* dlp = dl + (size_t)z * dstLS;
    #pragma unroll
    for (int i = 0; i < 32; i += 8) {
        float v = t[threadIdx.x][threadIdx.y + i];
        __nv_bfloat16 hh, ll; split2(v, hh, ll);
        size_t di = (size_t)(nt + threadIdx.y + i) * K + kt + threadIdx.x;
        dhp[di] = hh; dlp[di] = ll;
    }
}

// ---------------- LayerNorm: one warp per token, emits bf16 hi/lo ----------------
__global__ void ln_kernel(const float* __restrict__ x,
                          const float* __restrict__ gam,
                          const float* __restrict__ bet,
                          __nv_bfloat16* __restrict__ oh,
                          __nv_bfloat16* __restrict__ ol) {
    int warp = threadIdx.x >> 5, lane = threadIdx.x & 31;
    int token = blockIdx.x * 8 + warp;
    const float4* xr = (const float4*)(x + (size_t)token * D);
    float4 v0 = xr[lane];
    float4 v1 = xr[lane + 32];
    float s = v0.x + v0.y + v0.z + v0.w + v1.x + v1.y + v1.z + v1.w;
    #pragma unroll
    for (int o = 16; o > 0; o >>= 1) s += __shfl_xor_sync(0xffffffffu, s, o);
    float mu = s * (1.0f / 256.0f);
    float d0x = v0.x - mu, d0y = v0.y - mu, d0z = v0.z - mu, d0w = v0.w - mu;
    float d1x = v1.x - mu, d1y = v1.y - mu, d1z = v1.z - mu, d1w = v1.w - mu;
    float ss = d0x*d0x + d0y*d0y + d0z*d0z + d0w*d0w
             + d1x*d1x + d1y*d1y + d1z*d1z + d1w*d1w;
    #pragma unroll
    for (int o = 16; o > 0; o >>= 1) ss += __shfl_xor_sync(0xffffffffu, ss, o);
    float inv = rsqrtf(ss * (1.0f / 256.0f) + 1e-6f);
    float4 g0 = ((const float4*)gam)[lane];
    float4 g1 = ((const float4*)gam)[lane + 32];
    float4 b0 = ((const float4*)bet)[lane];
    float4 b1 = ((const float4*)bet)[lane + 32];
    float o00 = d0x * inv * g0.x + b0.x, o01 = d0y * inv * g0.y + b0.y;
    float o02 = d0z * inv * g0.z + b0.z, o03 = d0w * inv * g0.w + b0.w;
    float o10 = d1x * inv * g1.x + b1.x, o11 = d1y * inv * g1.y + b1.y;
    float o12 = d1z * inv * g1.z + b1.z, o13 = d1w * inv * g1.w + b1.w;
    __nv_bfloat16 h0,l0,h1,l1,h2,l2,h3,l3;
    size_t base = (size_t)token * D + lane * 4;
    split2(o00,h0,l0); split2(o01,h1,l1); split2(o02,h2,l2); split2(o03,h3,l3);
    *(__nv_bfloat162*)(oh + base)     = __nv_bfloat162(h0,h1);
    *(__nv_bfloat162*)(oh + base + 2) = __nv_bfloat162(h2,h3);
    *(__nv_bfloat162*)(ol + base)     = __nv_bfloat162(l0,l1);
    *(__nv_bfloat162*)(ol + base + 2) = __nv_bfloat162(l2,l3);
    split2(o10,h0,l0); split2(o11,h1,l1); split2(o12,h2,l2); split2(o13,h3,l3);
    *(__nv_bfloat162*)(oh + base + 128)     = __nv_bfloat162(h0,h1);
    *(__nv_bfloat162*)(oh + base + 128 + 2) = __nv_bfloat162(h2,h3);
    *(__nv_bfloat162*)(ol + base + 128)     = __nv_bfloat162(l0,l1);
    *(__nv_bfloat162*)(ol + base + 128 + 2) = __nv_bfloat162(l2,l3);
}

// ---------------- HMMA GEMM: C[M,N] = A[M,K] * Bt[N,K]^T ----------------
// A, Bt as hi/lo bf16 pairs. 128x128 CTA tile, 8 warps (2x4), warp 64x32.
// mma.sync m16n8k16 bf16, 3 split products into fp32 acc.
// K-chunk 64, 2-stage cp.async pipeline.
// EPI: 0 = QKV (bias select by blockIdx.x, fp32 out)
//      1 = gelu(acc+bias) -> bf16 hi/lo
//      2 = residual: Co += acc + bias
#define PITCHB 144                 /* 72 bf16 per row */
#define MATB   (128 * PITCHB)      /* 18432 */
#define STAGEB (4 * MATB)          /* 73728 */
#define GSMEM  (2 * STAGEB)        /* 147456 */

template<int EPI>
__global__ void __launch_bounds__(256, 1)
tc_gemm(const __nv_bfloat16* __restrict__ Ahi, const __nv_bfloat16* __restrict__ Alo,
        const __nv_bfloat16* __restrict__ Bthi, const __nv_bfloat16* __restrict__ Btlo,
        const float* __restrict__ bias0, const float* __restrict__ bias1,
        const float* __restrict__ bias2,
        float* __restrict__ Co,
        __nv_bfloat16* __restrict__ Chi, __nv_bfloat16* __restrict__ Clo,
        int K, int ldc) {
    extern __shared__ char smem[];
    uint32_t sb = smem_u32(smem);
    int tid = threadIdx.x;
    int wid = tid >> 5, lane = tid & 31;
    int wm = wid & 1, wn = wid >> 1;
    int row0 = blockIdx.y * 128, col0 = blockIdx.x * 128;

    float acc[4][4][4];
    #pragma unroll
    for (int a = 0; a < 4; a++)
        #pragma unroll
        for (int b = 0; b < 4; b++)
            #pragma unroll
            for (int c = 0; c < 4; c++) acc[a][b][c] = 0.0f;

    int arow = lane & 15, acolh = lane >> 4;
    int brow = ((lane >> 4) << 3) + (lane & 7), bkh = (lane >> 3) & 1;

    int nk = K >> 6;

    auto load_chunk = [&](int c) {
        int s = c & 1; int kc = c << 6;
        #pragma unroll
        for (int m = 0; m < 4; m++) {
            const __nv_bfloat16* src = (m == 0) ? Ahi : (m == 1) ? Alo : (m == 2) ? Bthi : Btlo;
            int rbase = (m < 2) ? row0 : col0;
            #pragma unroll
            for (int i = 0; i < 4; i++) {
                int idx = i * 256 + tid;          // 0..1023
                int r = idx >> 3, u = idx & 7;
                const void* g = src + (size_t)(rbase + r) * K + kc + u * 8;
                uint32_t dsh = sb + s * STAGEB + m * MATB + r * PITCHB + u * 16;
                cp16(dsh, g);
            }
        }
    };

    load_chunk(0); CP_COMMIT();
    for (int c = 0; c < nk; c++) {
        if (c + 1 < nk) load_chunk(c + 1);
        CP_COMMIT();
        CP_WAIT1();
        __syncthreads();
        uint32_t st = sb + (c & 1) * STAGEB;
        #pragma unroll
        for (int k16 = 0; k16 < 4; k16++) {
            uint32_t ah[4][4], al[4][4], bh[2][4], bl[2][4];
            #pragma unroll
            for (int mf = 0; mf < 4; mf++) {
                uint32_t ro = (uint32_t)(wm * 64 + mf * 16 + arow) * PITCHB + acolh * 16 + k16 * 32;
                ldsm4(ah[mf], st + ro);
                ldsm4(al[mf], st + MATB + ro);
            }
            #pragma unroll
            for (int g = 0; g < 2; g++) {
                uint32_t ro = (uint32_t)(wn * 32 + g * 16 + brow) * PITCHB + bkh * 16 + k16 * 32;
                ldsm4(bh[g], st + 2 * MATB + ro);
                ldsm4(bl[g], st + 3 * MATB + ro);
            }
            #pragma unroll
            for (int mf = 0; mf < 4; mf++)
                #pragma unroll
                for (int nf = 0; nf < 4; nf++) {
                    const uint32_t* bhp = &bh[nf >> 1][(nf & 1) * 2];
                    const uint32_t* blp = &bl[nf >> 1][(nf & 1) * 2];
                    mma_bf16(acc[mf][nf], ah[mf], bhp);
                    mma_bf16(acc[mf][nf], ah[mf], blp);
                    mma_bf16(acc[mf][nf], al[mf], bhp);
                }
        }
        __syncthreads();
    }

    // epilogue
    int qid = lane >> 2, tig = lane & 3;
    #pragma unroll
    for (int mf = 0; mf < 4; mf++) {
        #pragma unroll
        for (int rr = 0; rr < 2; rr++) {
            int grow = row0 + wm * 64 + mf * 16 + rr * 8 + qid;
            #pragma unroll
            for (int nf = 0; nf < 4; nf++) {
                int lcol = wn * 32 + nf * 8 + 2 * tig;   // 0..127 in tile
                float va = acc[mf][nf][rr * 2 + 0];
                float vb = acc[mf][nf][rr * 2 + 1];
                if (EPI == 0) {
                    int sel = blockIdx.x >> 1;
                    const float* bp = ((sel == 0) ? bias0 : (sel == 1) ? bias1 : bias2)
                                      + (blockIdx.x & 1) * 128 + lcol;
                    float2 r; r.x = va + bp[0]; r.y = vb + bp[1];
                    *(float2*)(Co + (size_t)grow * ldc + col0 + lcol) = r;
                } else if (EPI == 2) {
                    const float* bp = bias0 + col0 + lcol;
                    float2* cp = (float2*)(Co + (size_t)grow * ldc + col0 + lcol);
                    float2 old = *cp;
                    float2 r; r.x = old.x + va + bp[0]; r.y = old.y + vb + bp[1];
                    *cp = r;
                } else {
                    const float* bp = bias0 + col0 + lcol;
                    float ga = gelu_exact(va + bp[0]);
                    float gb = gelu_exact(vb + bp[1]);
                    __nv_bfloat16 ha, la, hb2, lb2;
                    split2(ga, ha, la); split2(gb, hb2, lb2);
                    *(__nv_bfloat162*)(Chi + (size_t)grow * ldc + col0 + lcol) = __nv_bfloat162(ha, hb2);
                    *(__nv_bfloat162*)(Clo + (size_t)grow * ldc + col0 + lcol) = __nv_bfloat162(la, lb2);
                }
            }
        }
    }
}

// ---------------- fused attention (qkv packed, stride 768) ----------------
#define KPAD 36

__global__ void __launch_bounds__(256)
attn_kernel(const float* __restrict__ qkv,
            const unsigned char* __restrict__ mask,
            __nv_bfloat16* __restrict__ aoh,
            __nv_bfloat16* __restrict__ aol) {
    extern __shared__ float sm[];
    float4* Ks4 = (float4*)sm;
    float4* Vs4 = (float4*)(sm + SEQ * KPAD);
    int bh = blockIdx.x;
    int b = bh >> 3, h = bh & 7;
    int tid = threadIdx.x;
    int warp = tid >> 5, lane = tid & 31;
    size_t base = (size_t)b * SEQ * 768 + (size_t)h * DK;

    for (int idx = tid; idx < SEQ * 8; idx += 256) {
        int j = idx >> 3, d4 = idx & 7;
        size_t gi = base + (size_t)j * 768 + d4 * 4;
        Ks4[j * 9 + d4] = *(const float4*)(qkv + gi + 256);
        Vs4[j * 9 + d4] = *(const float4*)(qkv + gi + 512);
    }
    __syncthreads();

    unsigned mbits = 0;
    #pragma unroll
    for (int t = 0; t < 14; t++)
        if (mask[b * SEQ + t * 32 + lane]) mbits |= (1u << t);

    const float scale = 0.17677669529663687f;

    for (int pp = warp * 28; pp < warp * 28 + 28; pp++) {
        int i0 = pp * 2, i1 = pp * 2 + 1;
        float q0[32], q1[32];
        {
            const float4* qp0 = (const float4*)(qkv + base + (size_t)i0 * 768);
            const float4* qp1 = (const float4*)(qkv + base + (size_t)i1 * 768);
            #pragma unroll
            for (int t4 = 0; t4 < 8; t4++) {
                float4 a = qp0[t4];
                q0[t4*4+0]=a.x; q0[t4*4+1]=a.y; q0[t4*4+2]=a.z; q0[t4*4+3]=a.w;
                float4 c = qp1[t4];
                q1[t4*4+0]=c.x; q1[t4*4+1]=c.y; q1[t4*4+2]=c.z; q1[t4*4+3]=c.w;
            }
        }
        float p0[14], p1[14];
        float mx0 = -1e30f, mx1 = -1e30f;
        #pragma unroll
        for (int t = 0; t < 14; t++) {
            int j = t * 32 + lane;
            const float4* kp = Ks4 + j * 9;
            float s0 = 0.0f, s1 = 0.0f;
            #pragma unroll
            for (int d4 = 0; d4 < 8; d4++) {
                float4 kk = kp[d4];
                s0 = fmaf(q0[d4*4+0], kk.x, s0); s0 = fmaf(q0[d4*4+1], kk.y, s0);
                s0 = fmaf(q0[d4*4+2], kk.z, s0); s0 = fmaf(q0[d4*4+3], kk.w, s0);
                s1 = fmaf(q1[d4*4+0], kk.x, s1); s1 = fmaf(q1[d4*4+1], kk.y, s1);
                s1 = fmaf(q1[d4*4+2], kk.z, s1); s1 = fmaf(q1[d4*4+3], kk.w, s1);
            }
            s0 *= scale; s1 *= scale;
            if ((mbits >> t) & 1u) { s0 = -10000.0f; s1 = -10000.0f; }
            p0[t] = s0; p1[t] = s1;
            mx0 = fmaxf(mx0, s0); mx1 = fmaxf(mx1, s1);
        }
        #pragma unroll
        for (int off = 16; off > 0; off >>= 1) {
            mx0 = fmaxf(mx0, __shfl_xor_sync(0xffffffffu, mx0, off));
            mx1 = fmaxf(mx1, __shfl_xor_sync(0xffffffffu, mx1, off));
        }
        float sum0 = 0.0f, sum1 = 0.0f;
        #pragma unroll
        for (int t = 0; t < 14; t++) {
            p0[t] = __expf(p0[t] - mx0); sum0 += p0[t];
            p1[t] = __expf(p1[t] - mx1); sum1 += p1[t];
        }
        #pragma unroll
        for (int off = 16; off > 0; off >>= 1) {
            sum0 += __shfl_xor_sync(0xffffffffu, sum0, off);
            sum1 += __shfl_xor_sync(0xffffffffu, sum1, off);
        }
        float inv0 = 1.0f / sum0, inv1 = 1.0f / sum1;

        float acc0[32], acc1[32];
        #pragma unroll
        for (int c = 0; c < 32; c++) { acc0[c] = 0.0f; acc1[c] = 0.0f; }
        #pragma unroll
        for (int t = 0; t < 14; t++) {
            int j = t * 32 + lane;
            const float4* vp = Vs4 + j * 9;
            float w0 = p0[t], w1 = p1[t];
            #pragma unroll
            for (int d4 = 0; d4 < 8; d4++) {
                float4 vv = vp[d4];
                acc0[d4*4+0] = fmaf(w0, vv.x, acc0[d4*4+0]);
                acc0[d4*4+1] = fmaf(w0, vv.y, acc0[d4*4+1]);
                acc0[d4*4+2] = fmaf(w0, vv.z, acc0[d4*4+2]);
                acc0[d4*4+3] = fmaf(w0, vv.w, acc0[d4*4+3]);
                acc1[d4*4+0] = fmaf(w1, vv.x, acc1[d4*4+0]);
                acc1[d4*4+1] = fmaf(w1, vv.y, acc1[d4*4+1]);
                acc1[d4*4+2] = fmaf(w1, vv.z, acc1[d4*4+2]);
                acc1[d4*4+3] = fmaf(w1, vv.w, acc1[d4*4+3]);
            }
        }
        #pragma unroll
        for (int half = 16; half >= 1; half >>= 1) {
            bool up = (lane & half) != 0;
            #pragma unroll
            for (int c = 0; c < half; c++) {
                float mine0 = up ? acc0[c + half] : acc0[c];
                float send0 = up ? acc0[c]        : acc0[c + half];
                float mine1 = up ? acc1[c + half] : acc1[c];
                float send1 = up ? acc1[c]        : acc1[c + half];
                acc0[c] = mine0 + __shfl_xor_sync(0xffffffffu, send0, half);
                acc1[c] = mine1 + __shfl_xor_sync(0xffffffffu, send1, half);
            }
        }
        float v0 = acc0[0] * inv0, v1 = acc1[0] * inv1;
        __nv_bfloat16 hh, ll;
        size_t t0 = (size_t)(b * SEQ + i0) * D + h * DK + lane;
        size_t t1 = (size_t)(b * SEQ + i1) * D + h * DK + lane;
        split2(v0, hh, ll); aoh[t0] = hh; aol[t0] = ll;
        split2(v1, hh, ll); aoh[t1] = hh; aol[t1] = ll;
    }
}

// ---------------- launch ----------------
extern "C" void kernel_launch(void* const* d_in, const int* in_sizes, int n_in,
                              void* d_out, int out_size) {
    const float* x_in = (const float*)d_in[0];
    const unsigned char* mask = (const unsigned char*)d_in[1];
    const float* pos  = (const float*)d_in[2];
    const float* Wq   = (const float*)d_in[3];
    const float* bq   = (const float*)d_in[4];
    const float* Wk   = (const float*)d_in[5];
    const float* bk   = (const float*)d_in[6];
    const float* Wv   = (const float*)d_in[7];
    const float* bv   = (const float*)d_in[8];
    const float* Wo   = (const float*)d_in[9];
    const float* bo   = (const float*)d_in[10];
    const float* W1   = (const float*)d_in[11];
    const float* bf1  = (const float*)d_in[12];
    const float* W2   = (const float*)d_in[13];
    const float* bf2  = (const float*)d_in[14];
    const float* ln1g = (const float*)d_in[15];
    const float* ln1b = (const float*)d_in[16];
    const float* ln2g = (const float*)d_in[17];
    const float* ln2b = (const float*)d_in[18];
    float* x = (float*)d_out;

    float* qkv;
    __nv_bfloat16 *nxh, *nxl, *aoh, *aol, *hh, *hl;
    __nv_bfloat16 *wqkvh, *wqkvl, *woth, *wotl, *w1th, *w1tl, *w2th, *w2tl;
    cudaGetSymbolAddress((void**)&qkv, g_qkv);
    cudaGetSymbolAddress((void**)&nxh, g_nxh);  cudaGetSymbolAddress((void**)&nxl, g_nxl);
    cudaGetSymbolAddress((void**)&aoh, g_aoh);  cudaGetSymbolAddress((void**)&aol, g_aol);
    cudaGetSymbolAddress((void**)&hh,  g_hh);   cudaGetSymbolAddress((void**)&hl,  g_hl);
    cudaGetSymbolAddress((void**)&wqkvh, g_wqkvh); cudaGetSymbolAddress((void**)&wqkvl, g_wqkvl);
    cudaGetSymbolAddress((void**)&woth,  g_woth);  cudaGetSymbolAddress((void**)&wotl,  g_wotl);
    cudaGetSymbolAddress((void**)&w1th,  g_w1th);  cudaGetSymbolAddress((void**)&w1tl,  g_w1tl);
    cudaGetSymbolAddress((void**)&w2th,  g_w2th);  cudaGetSymbolAddress((void**)&w2tl,  g_w2tl);

    int smem_attn = 2 * SEQ * KPAD * sizeof(float);
    cudaFuncSetAttribute(attn_kernel, cudaFuncAttributeMaxDynamicSharedMemorySize, smem_attn);
    cudaFuncSetAttribute(tc_gemm<0>, cudaFuncAttributeMaxDynamicSharedMemorySize, GSMEM);
    cudaFuncSetAttribute(tc_gemm<1>, cudaFuncAttributeMaxDynamicSharedMemorySize, GSMEM);
    cudaFuncSetAttribute(tc_gemm<2>, cudaFuncAttributeMaxDynamicSharedMemorySize, GSMEM);

    // weight prep (per replay; ~75MB traffic, negligible)
    wsplit_kernel<<<dim3(8, 8, NLAYERS),  dim3(32, 8)>>>(Wq, wqkvh,           wqkvl,           D, D, 768 * D);
    wsplit_kernel<<<dim3(8, 8, NLAYERS),  dim3(32, 8)>>>(Wk, wqkvh + 256 * D, wqkvl + 256 * D, D, D, 768 * D);
    wsplit_kernel<<<dim3(8, 8, NLAYERS),  dim3(32, 8)>>>(Wv, wqkvh + 512 * D, wqkvl + 512 * D, D, D, 768 * D);
    wsplit_kernel<<<dim3(8, 8, NLAYERS),  dim3(32, 8)>>>(Wo, woth, wotl, D, D, D * D);
    wsplit_kernel<<<dim3(32, 8, NLAYERS), dim3(32, 8)>>>(W1, w1th, w1tl, D, FFD, (size_t)FFD * D);
    wsplit_kernel<<<dim3(8, 32, NLAYERS), dim3(32, 8)>>>(W2, w2th, w2tl, FFD, D, (size_t)D * FFD);

    add_pos_kernel<<<(NTOK * D / 4) / 256, 256>>>(x_in, pos, x);

    for (int l = 0; l < NLAYERS; l++) {
        ln_kernel<<<NTOK / 8, 256>>>(x, ln1g + l * D, ln1b + l * D, nxh, nxl);

        tc_gemm<0><<<dim3(6, 112), 256, GSMEM>>>(
            nxh, nxl, wqkvh + (size_t)l * 768 * D, wqkvl + (size_t)l * 768 * D,
            bq + l * D, bk + l * D, bv + l * D,
            qkv, nullptr, nullptr, D, 768);

        attn_kernel<<<BATCH * H, 256, smem_attn>>>(qkv, mask, aoh, aol);

        tc_gemm<2><<<dim3(2, 112), 256, GSMEM>>>(
            aoh, aol, woth + (size_t)l * D * D, wotl + (size_t)l * D * D,
            bo + l * D, nullptr, nullptr,
            x, nullptr, nullptr, D, D);

        ln_kernel<<<NTOK / 8, 256>>>(x, ln2g + l * D, ln2b + l * D, nxh, nxl);

        tc_gemm<1><<<dim3(8, 112), 256, GSMEM>>>(
            nxh, nxl, w1th + (size_t)l * FFD * D, w1tl + (size_t)l * FFD * D,
            bf1 + l * FFD, nullptr, nullptr,
            nullptr, hh, hl, D, FFD);

        tc_gemm<2><<<dim3(2, 112), 256, GSMEM>>>(
            hh, hl, w2th + (size_t)l * D * FFD, w2tl + (size_t)l * D * FFD,
            bf2 + l * D, nullptr, nullptr,
            x, nullptr, nullptr, FFD, D);
    }
}

// round 7
// speedup vs baseline: 1.5104x; 1.5104x over previous
#include <cuda_runtime.h>
#include <cuda_bf16.h>
#include <math.h>
#include <stdint.h>

#define NLAYERS 12
#define D 256
#define H 8
#define DK 32
#define FFD 1024
#define BATCH 32
#define SEQ 448
#define NTOK (BATCH*SEQ)   /* 14336 */

// ---------------- scratch (no allocations allowed) ----------------
__device__ float g_qkv[NTOK * 768];
__device__ __nv_bfloat16 g_nxh[NTOK * D], g_nxl[NTOK * D];
__device__ __nv_bfloat16 g_aoh[NTOK * D], g_aol[NTOK * D];
__device__ __nv_bfloat16 g_hh [NTOK * FFD], g_hl [NTOK * FFD];
// transposed + split weights
__device__ __nv_bfloat16 g_wqkvh[NLAYERS * 768 * D], g_wqkvl[NLAYERS * 768 * D];
__device__ __nv_bfloat16 g_woth [NLAYERS * D * D],   g_wotl [NLAYERS * D * D];
__device__ __nv_bfloat16 g_w1th [NLAYERS * FFD * D], g_w1tl [NLAYERS * FFD * D];
__device__ __nv_bfloat16 g_w2th [NLAYERS * D * FFD], g_w2tl [NLAYERS * D * FFD];

// ---------------- helpers ----------------
__device__ __forceinline__ uint32_t smem_u32(const void* p) {
    uint32_t a;
    asm("{ .reg .u64 t; cvta.to.shared.u64 t, %1; cvt.u32.u64 %0, t; }" : "=r"(a) : "l"(p));
    return a;
}
__device__ __forceinline__ void cp16(uint32_t dst, const void* src) {
    asm volatile("cp.async.ca.shared.global [%0], [%1], 16;" :: "r"(dst), "l"(src));
}
#define CP_COMMIT() asm volatile("cp.async.commit_group;" ::: "memory")
#define CP_WAIT1()  asm volatile("cp.async.wait_group 1;" ::: "memory")

__device__ __forceinline__ void ldsm4(uint32_t* r, uint32_t addr) {
    asm volatile("ldmatrix.sync.aligned.m8n8.x4.shared.b16 {%0,%1,%2,%3}, [%4];"
        : "=r"(r[0]), "=r"(r[1]), "=r"(r[2]), "=r"(r[3]) : "r"(addr));
}
__device__ __forceinline__ void mma_bf16(float* d, const uint32_t* a, const uint32_t* b) {
    asm volatile(
        "mma.sync.aligned.m16n8k16.row.col.f32.bf16.bf16.f32 "
        "{%0,%1,%2,%3}, {%4,%5,%6,%7}, {%8,%9}, {%0,%1,%2,%3};"
        : "+f"(d[0]), "+f"(d[1]), "+f"(d[2]), "+f"(d[3])
        : "r"(a[0]), "r"(a[1]), "r"(a[2]), "r"(a[3]), "r"(b[0]), "r"(b[1]));
}
__device__ __forceinline__ void split2(float v, __nv_bfloat16& h, __nv_bfloat16& l) {
    h = __float2bfloat16(v);
    l = __float2bfloat16(v - __bfloat162float(h));
}
__device__ __forceinline__ float gelu_exact(float x) {
    return 0.5f * x * (1.0f + erff(x * 0.7071067811865475f));
}

// ---------------- weight transpose + hi/lo split ----------------
// Generic: src W [K,N] fp32, layer stride K*N; dst [N,K] bf16 at dstLS stride.
__global__ void wsplit_kernel(const float* __restrict__ W,
                              __nv_bfloat16* __restrict__ dh,
                              __nv_bfloat16* __restrict__ dl,
                              int K, int N, size_t dstLS) {
    __shared__ float t[32][33];
    int z = blockIdx.z;
    int nt = blockIdx.x * 32, kt = blockIdx.y * 32;
    const float* src = W + (size_t)z * K * N;
    #pragma unroll
    for (int i = 0; i < 32; i += 8)
        t[threadIdx.y + i][threadIdx.x] = src[(size_t)(kt + threadIdx.y + i) * N + nt + threadIdx.x];
    __syncthreads();
    __nv_bfloat16* dhp = dh + (size_t)z * dstLS;
    __nv_bfloat16* dlp = dl + (size_t)z * dstLS;
    #pragma unroll
    for (int i = 0; i < 32; i += 8) {
        float v = t[threadIdx.x][threadIdx.y + i];
        __nv_bfloat16 hh, ll; split2(v, hh, ll);
        size_t di = (size_t)(nt + threadIdx.y + i) * K + kt + threadIdx.x;
        dhp[di] = hh; dlp[di] = ll;
    }
}

// QKV merged: z in [0, 3*NLAYERS): layer = z/3, which = z%3 selects Wq/Wk/Wv.
__global__ void wsplit_qkv_kernel(const float* __restrict__ Wq,
                                  const float* __restrict__ Wk,
                                  const float* __restrict__ Wv,
                                  __nv_bfloat16* __restrict__ dh,
                                  __nv_bfloat16* __restrict__ dl) {
    __shared__ float t[32][33];
    int z = blockIdx.z;
    int layer = z / 3, which = z % 3;
    const float* src = ((which == 0) ? Wq : (which == 1) ? Wk : Wv) + (size_t)layer * D * D;
    int nt = blockIdx.x * 32, kt = blockIdx.y * 32;
    #pragma unroll
    for (int i = 0; i < 32; i += 8)
        t[threadIdx.y + i][threadIdx.x] = src[(size_t)(kt + threadIdx.y + i) * D + nt + threadIdx.x];
    __syncthreads();
    size_t dbase = (size_t)layer * 768 * D + (size_t)which * 256 * D;
    #pragma unroll
    for (int i = 0; i < 32; i += 8) {
        float v = t[threadIdx.x][threadIdx.y + i];
        __nv_bfloat16 hh, ll; split2(v, hh, ll);
        size_t di = dbase + (size_t)(nt + threadIdx.y + i) * D + kt + threadIdx.x;
        dh[di] = hh; dl[di] = ll;
    }
}

// ---------------- LayerNorm core ----------------
__device__ __forceinline__ void ln_row(float4 v0, float4 v1,
                                       const float* gam, const float* bet, int lane,
                                       __nv_bfloat16* oh, __nv_bfloat16* ol, size_t base) {
    float s = v0.x + v0.y + v0.z + v0.w + v1.x + v1.y + v1.z + v1.w;
    #pragma unroll
    for (int o = 16; o > 0; o >>= 1) s += __shfl_xor_sync(0xffffffffu, s, o);
    float mu = s * (1.0f / 256.0f);
    float d0x = v0.x - mu, d0y = v0.y - mu, d0z = v0.z - mu, d0w = v0.w - mu;
    float d1x = v1.x - mu, d1y = v1.y - mu, d1z = v1.z - mu, d1w = v1.w - mu;
    float ss = d0x*d0x + d0y*d0y + d0z*d0z + d0w*d0w
             + d1x*d1x + d1y*d1y + d1z*d1z + d1w*d1w;
    #pragma unroll
    for (int o = 16; o > 0; o >>= 1) ss += __shfl_xor_sync(0xffffffffu, ss, o);
    float inv = rsqrtf(ss * (1.0f / 256.0f) + 1e-6f);
    float4 g0 = ((const float4*)gam)[lane];
    float4 g1 = ((const float4*)gam)[lane + 32];
    float4 b0 = ((const float4*)bet)[lane];
    float4 b1 = ((const float4*)bet)[lane + 32];
    float o00 = d0x * inv * g0.x + b0.x, o01 = d0y * inv * g0.y + b0.y;
    float o02 = d0z * inv * g0.z + b0.z, o03 = d0w * inv * g0.w + b0.w;
    float o10 = d1x * inv * g1.x + b1.x, o11 = d1y * inv * g1.y + b1.y;
    float o12 = d1z * inv * g1.z + b1.z, o13 = d1w * inv * g1.w + b1.w;
    __nv_bfloat16 h0,l0,h1,l1,h2,l2,h3,l3;
    split2(o00,h0,l0); split2(o01,h1,l1); split2(o02,h2,l2); split2(o03,h3,l3);
    *(__nv_bfloat162*)(oh + base)     = __nv_bfloat162(h0,h1);
    *(__nv_bfloat162*)(oh + base + 2) = __nv_bfloat162(h2,h3);
    *(__nv_bfloat162*)(ol + base)     = __nv_bfloat162(l0,l1);
    *(__nv_bfloat162*)(ol + base + 2) = __nv_bfloat162(l2,l3);
    split2(o10,h0,l0); split2(o11,h1,l1); split2(o12,h2,l2); split2(o13,h3,l3);
    *(__nv_bfloat162*)(oh + base + 128)     = __nv_bfloat162(h0,h1);
    *(__nv_bfloat162*)(oh + base + 128 + 2) = __nv_bfloat162(h2,h3);
    *(__nv_bfloat162*)(ol + base + 128)     = __nv_bfloat162(l0,l1);
    *(__nv_bfloat162*)(ol + base + 128 + 2) = __nv_bfloat162(l2,l3);
}

__global__ void ln_kernel(const float* __restrict__ x,
                          const float* __restrict__ gam,
                          const float* __restrict__ bet,
                          __nv_bfloat16* __restrict__ oh,
                          __nv_bfloat16* __restrict__ ol) {
    int warp = threadIdx.x >> 5, lane = threadIdx.x & 31;
    int token = blockIdx.x * 8 + warp;
    const float4* xr = (const float4*)(x + (size_t)token * D);
    float4 v0 = xr[lane];
    float4 v1 = xr[lane + 32];
    ln_row(v0, v1, gam, bet, lane, oh, ol, (size_t)token * D + lane * 4);
}

// fused: x = x_in + pos; then LN(x) -> hi/lo
__global__ void addpos_ln_kernel(const float* __restrict__ xin,
                                 const float* __restrict__ pos,
                                 float* __restrict__ xout,
                                 const float* __restrict__ gam,
                                 const float* __restrict__ bet,
                                 __nv_bfloat16* __restrict__ oh,
                                 __nv_bfloat16* __restrict__ ol) {
    int warp = threadIdx.x >> 5, lane = threadIdx.x & 31;
    int token = blockIdx.x * 8 + warp;
    int l = token % SEQ;
    const float4* xr = (const float4*)(xin + (size_t)token * D);
    const float4* pr = (const float4*)(pos + (size_t)l * D);
    float4 v0 = xr[lane],      p0 = pr[lane];
    float4 v1 = xr[lane + 32], p1 = pr[lane + 32];
    v0.x += p0.x; v0.y += p0.y; v0.z += p0.z; v0.w += p0.w;
    v1.x += p1.x; v1.y += p1.y; v1.z += p1.z; v1.w += p1.w;
    float4* xo = (float4*)(xout + (size_t)token * D);
    xo[lane] = v0; xo[lane + 32] = v1;
    ln_row(v0, v1, gam, bet, lane, oh, ol, (size_t)token * D + lane * 4);
}

// ---------------- HMMA GEMM v2: 512 threads, warp-tile 32x32 ----------------
// C[M,N] = A[M,K]*Bt[N,K]^T, hi/lo split (3 products), fp32 acc.
// 128x128 CTA tile, 16 warps (4x4), 2-stage cp.async, K-chunk 64.
// Product-major mma ordering for ILP-8 between accumulator reuses.
#define PITCHB 144                 /* 72 bf16 per row, conflict-free ldmatrix */
#define MATB   (128 * PITCHB)      /* 18432 */
#define STAGEB (4 * MATB)          /* 73728 */
#define GSMEM  (2 * STAGEB)        /* 147456 */

template<int EPI>
__global__ void __launch_bounds__(512, 1)
tc_gemm(const __nv_bfloat16* __restrict__ Ahi, const __nv_bfloat16* __restrict__ Alo,
        const __nv_bfloat16* __restrict__ Bthi, const __nv_bfloat16* __restrict__ Btlo,
        const float* __restrict__ bias0, const float* __restrict__ bias1,
        const float* __restrict__ bias2,
        float* __restrict__ Co,
        __nv_bfloat16* __restrict__ Chi, __nv_bfloat16* __restrict__ Clo,
        int K, int ldc) {
    extern __shared__ char smem[];
    uint32_t sb = smem_u32(smem);
    int tid = threadIdx.x;
    int wid = tid >> 5, lane = tid & 31;
    int wm = wid & 3, wn = wid >> 2;            // 4x4 warp grid, 32x32 tiles
    int row0 = blockIdx.y * 128, col0 = blockIdx.x * 128;

    float acc[2][4][4];
    #pragma unroll
    for (int a = 0; a < 2; a++)
        #pragma unroll
        for (int b = 0; b < 4; b++)
            #pragma unroll
            for (int c = 0; c < 4; c++) acc[a][b][c] = 0.0f;

    int arow = lane & 15, acolh = lane >> 4;
    int brow = ((lane >> 4) << 3) + (lane & 7), bkh = (lane >> 3) & 1;

    int nk = K >> 6;

    auto load_chunk = [&](int c) {
        int s = c & 1; int kc = c << 6;
        #pragma unroll
        for (int m = 0; m < 4; m++) {
            const __nv_bfloat16* src = (m == 0) ? Ahi : (m == 1) ? Alo : (m == 2) ? Bthi : Btlo;
            int rbase = (m < 2) ? row0 : col0;
            #pragma unroll
            for (int i = 0; i < 2; i++) {
                int idx = i * 512 + tid;          // 0..1023 (16B units)
                int r = idx >> 3, u = idx & 7;
                const void* g = src + (size_t)(rbase + r) * K + kc + u * 8;
                uint32_t dsh = sb + s * STAGEB + m * MATB + r * PITCHB + u * 16;
                cp16(dsh, g);
            }
        }
    };

    load_chunk(0); CP_COMMIT();
    for (int c = 0; c < nk; c++) {
        if (c + 1 < nk) load_chunk(c + 1);
        CP_COMMIT();
        CP_WAIT1();
        __syncthreads();
        uint32_t st = sb + (c & 1) * STAGEB;
        #pragma unroll
        for (int k16 = 0; k16 < 4; k16++) {
            uint32_t ah[2][4], al[2][4], bh[2][4], bl[2][4];
            #pragma unroll
            for (int mf = 0; mf < 2; mf++) {
                uint32_t ro = (uint32_t)(wm * 32 + mf * 16 + arow) * PITCHB + acolh * 16 + k16 * 32;
                ldsm4(ah[mf], st + ro);
                ldsm4(al[mf], st + MATB + ro);
            }
            #pragma unroll
            for (int g = 0; g < 2; g++) {
                uint32_t ro = (uint32_t)(wn * 32 + g * 16 + brow) * PITCHB + bkh * 16 + k16 * 32;
                ldsm4(bh[g], st + 2 * MATB + ro);
                ldsm4(bl[g], st + 3 * MATB + ro);
            }
            // product-major: 8 independent accs between same-acc reuse
            #pragma unroll
            for (int mf = 0; mf < 2; mf++)
                #pragma unroll
                for (int nf = 0; nf < 4; nf++)
                    mma_bf16(acc[mf][nf], ah[mf], &bh[nf >> 1][(nf & 1) * 2]);
            #pragma unroll
            for (int mf = 0; mf < 2; mf++)
                #pragma unroll
                for (int nf = 0; nf < 4; nf++)
                    mma_bf16(acc[mf][nf], ah[mf], &bl[nf >> 1][(nf & 1) * 2]);
            #pragma unroll
            for (int mf = 0; mf < 2; mf++)
                #pragma unroll
                for (int nf = 0; nf < 4; nf++)
                    mma_bf16(acc[mf][nf], al[mf], &bh[nf >> 1][(nf & 1) * 2]);
        }
        __syncthreads();
    }

    // epilogue
    int qid = lane >> 2, tig = lane & 3;
    #pragma unroll
    for (int mf = 0; mf < 2; mf++) {
        #pragma unroll
        for (int rr = 0; rr < 2; rr++) {
            int grow = row0 + wm * 32 + mf * 16 + rr * 8 + qid;
            #pragma unroll
            for (int nf = 0; nf < 4; nf++) {
                int lcol = wn * 32 + nf * 8 + 2 * tig;   // 0..127 in tile
                float va = acc[mf][nf][rr * 2 + 0];
                float vb = acc[mf][nf][rr * 2 + 1];
                if (EPI == 0) {
                    int sel = blockIdx.x >> 1;
                    const float* bp = ((sel == 0) ? bias0 : (sel == 1) ? bias1 : bias2)
                                      + (blockIdx.x & 1) * 128 + lcol;
                    float2 r; r.x = va + bp[0]; r.y = vb + bp[1];
                    *(float2*)(Co + (size_t)grow * ldc + col0 + lcol) = r;
                } else if (EPI == 2) {
                    const float* bp = bias0 + col0 + lcol;
                    float2* cp = (float2*)(Co + (size_t)grow * ldc + col0 + lcol);
                    float2 old = *cp;
                    float2 r; r.x = old.x + va + bp[0]; r.y = old.y + vb + bp[1];
                    *cp = r;
                } else {
                    const float* bp = bias0 + col0 + lcol;
                    float ga = gelu_exact(va + bp[0]);
                    float gb = gelu_exact(vb + bp[1]);
                    __nv_bfloat16 ha, la, hb2, lb2;
                    split2(ga, ha, la); split2(gb, hb2, lb2);
                    *(__nv_bfloat162*)(Chi + (size_t)grow * ldc + col0 + lcol) = __nv_bfloat162(ha, hb2);
                    *(__nv_bfloat162*)(Clo + (size_t)grow * ldc + col0 + lcol) = __nv_bfloat162(la, lb2);
                }
            }
        }
    }
}

// ---------------- fused attention (qkv packed, stride 768) ----------------
#define KPAD 36

__global__ void __launch_bounds__(256)
attn_kernel(const float* __restrict__ qkv,
            const unsigned char* __restrict__ mask,
            __nv_bfloat16* __restrict__ aoh,
            __nv_bfloat16* __restrict__ aol) {
    extern __shared__ float sm[];
    float4* Ks4 = (float4*)sm;
    float4* Vs4 = (float4*)(sm + SEQ * KPAD);
    int bh = blockIdx.x;
    int b = bh >> 3, h = bh & 7;
    int tid = threadIdx.x;
    int warp = tid >> 5, lane = tid & 31;
    size_t base = (size_t)b * SEQ * 768 + (size_t)h * DK;

    for (int idx = tid; idx < SEQ * 8; idx += 256) {
        int j = idx >> 3, d4 = idx & 7;
        size_t gi = base + (size_t)j * 768 + d4 * 4;
        Ks4[j * 9 + d4] = *(const float4*)(qkv + gi + 256);
        Vs4[j * 9 + d4] = *(const float4*)(qkv + gi + 512);
    }
    __syncthreads();

    unsigned mbits = 0;
    #pragma unroll
    for (int t = 0; t < 14; t++)
        if (mask[b * SEQ + t * 32 + lane]) mbits |= (1u << t);

    const float scale = 0.17677669529663687f;

    for (int pp = warp * 28; pp < warp * 28 + 28; pp++) {
        int i0 = pp * 2, i1 = pp * 2 + 1;
        float q0[32], q1[32];
        {
            const float4* qp0 = (const float4*)(qkv + base + (size_t)i0 * 768);
            const float4* qp1 = (const float4*)(qkv + base + (size_t)i1 * 768);
            #pragma unroll
            for (int t4 = 0; t4 < 8; t4++) {
                float4 a = qp0[t4];
                q0[t4*4+0]=a.x; q0[t4*4+1]=a.y; q0[t4*4+2]=a.z; q0[t4*4+3]=a.w;
                float4 c = qp1[t4];
                q1[t4*4+0]=c.x; q1[t4*4+1]=c.y; q1[t4*4+2]=c.z; q1[t4*4+3]=c.w;
            }
        }
        float p0[14], p1[14];
        float mx0 = -1e30f, mx1 = -1e30f;
        #pragma unroll
        for (int t = 0; t < 14; t++) {
            int j = t * 32 + lane;
            const float4* kp = Ks4 + j * 9;
            float s0 = 0.0f, s1 = 0.0f;
            #pragma unroll
            for (int d4 = 0; d4 < 8; d4++) {
                float4 kk = kp[d4];
                s0 = fmaf(q0[d4*4+0], kk.x, s0); s0 = fmaf(q0[d4*4+1], kk.y, s0);
                s0 = fmaf(q0[d4*4+2], kk.z, s0); s0 = fmaf(q0[d4*4+3], kk.w, s0);
                s1 = fmaf(q1[d4*4+0], kk.x, s1); s1 = fmaf(q1[d4*4+1], kk.y, s1);
                s1 = fmaf(q1[d4*4+2], kk.z, s1); s1 = fmaf(q1[d4*4+3], kk.w, s1);
            }
            s0 *= scale; s1 *= scale;
            if ((mbits >> t) & 1u) { s0 = -10000.0f; s1 = -10000.0f; }
            p0[t] = s0; p1[t] = s1;
            mx0 = fmaxf(mx0, s0); mx1 = fmaxf(mx1, s1);
        }
        #pragma unroll
        for (int off = 16; off > 0; off >>= 1) {
            mx0 = fmaxf(mx0, __shfl_xor_sync(0xffffffffu, mx0, off));
            mx1 = fmaxf(mx1, __shfl_xor_sync(0xffffffffu, mx1, off));
        }
        float sum0 = 0.0f, sum1 = 0.0f;
        #pragma unroll
        for (int t = 0; t < 14; t++) {
            p0[t] = __expf(p0[t] - mx0); sum0 += p0[t];
            p1[t] = __expf(p1[t] - mx1); sum1 += p1[t];
        }
        #pragma unroll
        for (int off = 16; off > 0; off >>= 1) {
            sum0 += __shfl_xor_sync(0xffffffffu, sum0, off);
            sum1 += __shfl_xor_sync(0xffffffffu, sum1, off);
        }
        float inv0 = 1.0f / sum0, inv1 = 1.0f / sum1;

        float acc0[32], acc1[32];
        #pragma unroll
        for (int c = 0; c < 32; c++) { acc0[c] = 0.0f; acc1[c] = 0.0f; }
        #pragma unroll
        for (int t = 0; t < 14; t++) {
            int j = t * 32 + lane;
            const float4* vp = Vs4 + j * 9;
            float w0 = p0[t], w1 = p1[t];
            #pragma unroll
            for (int d4 = 0; d4 < 8; d4++) {
                float4 vv = vp[d4];
                acc0[d4*4+0] = fmaf(w0, vv.x, acc0[d4*4+0]);
                acc0[d4*4+1] = fmaf(w0, vv.y, acc0[d4*4+1]);
                acc0[d4*4+2] = fmaf(w0, vv.z, acc0[d4*4+2]);
                acc0[d4*4+3] = fmaf(w0, vv.w, acc0[d4*4+3]);
                acc1[d4*4+0] = fmaf(w1, vv.x, acc1[d4*4+0]);
                acc1[d4*4+1] = fmaf(w1, vv.y, acc1[d4*4+1]);
                acc1[d4*4+2] = fmaf(w1, vv.z, acc1[d4*4+2]);
                acc1[d4*4+3] = fmaf(w1, vv.w, acc1[d4*4+3]);
            }
        }
        #pragma unroll
        for (int half = 16; half >= 1; half >>= 1) {
            bool up = (lane & half) != 0;
            #pragma unroll
            for (int c = 0; c < half; c++) {
                float mine0 = up ? acc0[c + half] : acc0[c];
                float send0 = up ? acc0[c]        : acc0[c + half];
                float mine1 = up ? acc1[c + half] : acc1[c];
                float send1 = up ? acc1[c]        : acc1[c + half];
                acc0[c] = mine0 + __shfl_xor_sync(0xffffffffu, send0, half);
                acc1[c] = mine1 + __shfl_xor_sync(0xffffffffu, send1, half);
            }
        }
        float v0 = acc0[0] * inv0, v1 = acc1[0] * inv1;
        __nv_bfloat16 hh, ll;
        size_t t0 = (size_t)(b * SEQ + i0) * D + h * DK + lane;
        size_t t1 = (size_t)(b * SEQ + i1) * D + h * DK + lane;
        split2(v0, hh, ll); aoh[t0] = hh; aol[t0] = ll;
        split2(v1, hh, ll); aoh[t1] = hh; aol[t1] = ll;
    }
}

// ---------------- launch ----------------
extern "C" void kernel_launch(void* const* d_in, const int* in_sizes, int n_in,
                              void* d_out, int out_size) {
    const float* x_in = (const float*)d_in[0];
    const unsigned char* mask = (const unsigned char*)d_in[1];
    const float* pos  = (const float*)d_in[2];
    const float* Wq   = (const float*)d_in[3];
    const float* bq   = (const float*)d_in[4];
    const float* Wk   = (const float*)d_in[5];
    const float* bk   = (const float*)d_in[6];
    const float* Wv   = (const float*)d_in[7];
    const float* bv   = (const float*)d_in[8];
    const float* Wo   = (const float*)d_in[9];
    const float* bo   = (const float*)d_in[10];
    const float* W1   = (const float*)d_in[11];
    const float* bf1  = (const float*)d_in[12];
    const float* W2   = (const float*)d_in[13];
    const float* bf2  = (const float*)d_in[14];
    const float* ln1g = (const float*)d_in[15];
    const float* ln1b = (const float*)d_in[16];
    const float* ln2g = (const float*)d_in[17];
    const float* ln2b = (const float*)d_in[18];
    float* x = (float*)d_out;

    float* qkv;
    __nv_bfloat16 *nxh, *nxl, *aoh, *aol, *hh, *hl;
    __nv_bfloat16 *wqkvh, *wqkvl, *woth, *wotl, *w1th, *w1tl, *w2th, *w2tl;
    cudaGetSymbolAddress((void**)&qkv, g_qkv);
    cudaGetSymbolAddress((void**)&nxh, g_nxh);  cudaGetSymbolAddress((void**)&nxl, g_nxl);
    cudaGetSymbolAddress((void**)&aoh, g_aoh);  cudaGetSymbolAddress((void**)&aol, g_aol);
    cudaGetSymbolAddress((void**)&hh,  g_hh);   cudaGetSymbolAddress((void**)&hl,  g_hl);
    cudaGetSymbolAddress((void**)&wqkvh, g_wqkvh); cudaGetSymbolAddress((void**)&wqkvl, g_wqkvl);
    cudaGetSymbolAddress((void**)&woth,  g_woth);  cudaGetSymbolAddress((void**)&wotl,  g_wotl);
    cudaGetSymbolAddress((void**)&w1th,  g_w1th);  cudaGetSymbolAddress((void**)&w1tl,  g_w1tl);
    cudaGetSymbolAddress((void**)&w2th,  g_w2th);  cudaGetSymbolAddress((void**)&w2tl,  g_w2tl);

    int smem_attn = 2 * SEQ * KPAD * sizeof(float);
    cudaFuncSetAttribute(attn_kernel, cudaFuncAttributeMaxDynamicSharedMemorySize, smem_attn);
    cudaFuncSetAttribute(tc_gemm<0>, cudaFuncAttributeMaxDynamicSharedMemorySize, GSMEM);
    cudaFuncSetAttribute(tc_gemm<1>, cudaFuncAttributeMaxDynamicSharedMemorySize, GSMEM);
    cudaFuncSetAttribute(tc_gemm<2>, cudaFuncAttributeMaxDynamicSharedMemorySize, GSMEM);

    // weight prep: 4 launches (0-3)
    wsplit_qkv_kernel<<<dim3(8, 8, 3 * NLAYERS), dim3(32, 8)>>>(Wq, Wk, Wv, wqkvh, wqkvl);
    wsplit_kernel<<<dim3(8, 8, NLAYERS),  dim3(32, 8)>>>(Wo, woth, wotl, D, D, D * D);
    wsplit_kernel<<<dim3(32, 8, NLAYERS), dim3(32, 8)>>>(W1, w1th, w1tl, D, FFD, (size_t)FFD * D);
    wsplit_kernel<<<dim3(8, 32, NLAYERS), dim3(32, 8)>>>(W2, w2th, w2tl, FFD, D, (size_t)D * FFD);

    for (int l = 0; l < NLAYERS; l++) {
        if (l == 0) {
            // launch 4: fused pos-emb + LN1  -> launch 5 is tc_gemm<0> (ncu capture slot)
            addpos_ln_kernel<<<NTOK / 8, 256>>>(x_in, pos, x,
                                                ln1g, ln1b, nxh, nxl);
        } else {
            ln_kernel<<<NTOK / 8, 256>>>(x, ln1g + l * D, ln1b + l * D, nxh, nxl);
        }

        tc_gemm<0><<<dim3(6, 112), 512, GSMEM>>>(
            nxh, nxl, wqkvh + (size_t)l * 768 * D, wqkvl + (size_t)l * 768 * D,
            bq + l * D, bk + l * D, bv + l * D,
            qkv, nullptr, nullptr, D, 768);

        attn_kernel<<<BATCH * H, 256, smem_attn>>>(qkv, mask, aoh, aol);

        tc_gemm<2><<<dim3(2, 112), 512, GSMEM>>>(
            aoh, aol, woth + (size_t)l * D * D, wotl + (size_t)l * D * D,
            bo + l * D, nullptr, nullptr,
            x, nullptr, nullptr, D, D);

        ln_kernel<<<NTOK / 8, 256>>>(x, ln2g + l * D, ln2b + l * D, nxh, nxl);

        tc_gemm<1><<<dim3(8, 112), 512, GSMEM>>>(
            nxh, nxl, w1th + (size_t)l * FFD * D, w1tl + (size_t)l * FFD * D,
            bf1 + l * FFD, nullptr, nullptr,
            nullptr, hh, hl, D, FFD);

        tc_gemm<2><<<dim3(2, 112), 512, GSMEM>>>(
            hh, hl, w2th + (size_t)l * D * FFD, w2tl + (size_t)l * D * FFD,
            bf2 + l * D, nullptr, nullptr,
            x, nullptr, nullptr, FFD, D);
    }
}

// round 9
// speedup vs baseline: 2.5461x; 1.6857x over previous
#include <cuda_runtime.h>
#include <cuda_bf16.h>
#include <math.h>
#include <stdint.h>

#define NLAYERS 12
#define D 256
#define H 8
#define DK 32
#define FFD 1024
#define BATCH 32
#define SEQ 448
#define NTOK (BATCH*SEQ)   /* 14336 */

// ---------------- scratch (no allocations allowed) ----------------
__device__ float g_qkv[NTOK * 768];
__device__ __nv_bfloat16 g_nxh[NTOK * D], g_nxl[NTOK * D];
__device__ __nv_bfloat16 g_aoh[NTOK * D], g_aol[NTOK * D];
__device__ __nv_bfloat16 g_hh [NTOK * FFD], g_hl [NTOK * FFD];
// transposed + split weights
__device__ __nv_bfloat16 g_wqkvh[NLAYERS * 768 * D], g_wqkvl[NLAYERS * 768 * D];
__device__ __nv_bfloat16 g_woth [NLAYERS * D * D],   g_wotl [NLAYERS * D * D];
__device__ __nv_bfloat16 g_w1th [NLAYERS * FFD * D], g_w1tl [NLAYERS * FFD * D];
__device__ __nv_bfloat16 g_w2th [NLAYERS * D * FFD], g_w2tl [NLAYERS * D * FFD];

// ---------------- helpers ----------------
__device__ __forceinline__ uint32_t smem_u32(const void* p) {
    uint32_t a;
    asm("{ .reg .u64 t; cvta.to.shared.u64 t, %1; cvt.u32.u64 %0, t; }" : "=r"(a) : "l"(p));
    return a;
}
__device__ __forceinline__ void cp16(uint32_t dst, const void* src) {
    asm volatile("cp.async.ca.shared.global [%0], [%1], 16;" :: "r"(dst), "l"(src));
}
#define CP_COMMIT() asm volatile("cp.async.commit_group;" ::: "memory")
#define CP_WAIT1()  asm volatile("cp.async.wait_group 1;" ::: "memory")

__device__ __forceinline__ void ldsm4(uint32_t* r, uint32_t addr) {
    asm volatile("ldmatrix.sync.aligned.m8n8.x4.shared.b16 {%0,%1,%2,%3}, [%4];"
        : "=r"(r[0]), "=r"(r[1]), "=r"(r[2]), "=r"(r[3]) : "r"(addr));
}
__device__ __forceinline__ void ldsm4t(uint32_t* r, uint32_t addr) {
    asm volatile("ldmatrix.sync.aligned.m8n8.x4.trans.shared.b16 {%0,%1,%2,%3}, [%4];"
        : "=r"(r[0]), "=r"(r[1]), "=r"(r[2]), "=r"(r[3]) : "r"(addr));
}
__device__ __forceinline__ void mma_bf16(float* d, const uint32_t* a, const uint32_t* b) {
    asm volatile(
        "mma.sync.aligned.m16n8k16.row.col.f32.bf16.bf16.f32 "
        "{%0,%1,%2,%3}, {%4,%5,%6,%7}, {%8,%9}, {%0,%1,%2,%3};"
        : "+f"(d[0]), "+f"(d[1]), "+f"(d[2]), "+f"(d[3])
        : "r"(a[0]), "r"(a[1]), "r"(a[2]), "r"(a[3]), "r"(b[0]), "r"(b[1]));
}
__device__ __forceinline__ void split2(float v, __nv_bfloat16& h, __nv_bfloat16& l) {
    h = __float2bfloat16(v);
    l = __float2bfloat16(v - __bfloat162float(h));
}
__device__ __forceinline__ uint32_t pack2(__nv_bfloat16 a, __nv_bfloat16 b) {
    __nv_bfloat162 t(a, b);
    return *(uint32_t*)&t;
}
// pack hi parts of two floats; also return lo pack
__device__ __forceinline__ void packsplit(float x, float y, uint32_t& hi, uint32_t& lo) {
    __nv_bfloat16 hx, lx, hy, ly;
    split2(x, hx, lx); split2(y, hy, ly);
    hi = pack2(hx, hy); lo = pack2(lx, ly);
}
__device__ __forceinline__ float gelu_exact(float x) {
    return 0.5f * x * (1.0f + erff(x * 0.7071067811865475f));
}

// ---------------- weight transpose + hi/lo split ----------------
__global__ void wsplit_kernel(const float* __restrict__ W,
                              __nv_bfloat16* __restrict__ dh,
                              __nv_bfloat16* __restrict__ dl,
                              int K, int N, size_t dstLS) {
    __shared__ float t[32][33];
    int z = blockIdx.z;
    int nt = blockIdx.x * 32, kt = blockIdx.y * 32;
    const float* src = W + (size_t)z * K * N;
    #pragma unroll
    for (int i = 0; i < 32; i += 8)
        t[threadIdx.y + i][threadIdx.x] = src[(size_t)(kt + threadIdx.y + i) * N + nt + threadIdx.x];
    __syncthreads();
    __nv_bfloat16* dhp = dh + (size_t)z * dstLS;
    __nv_bfloat16* dlp = dl + (size_t)z * dstLS;
    #pragma unroll
    for (int i = 0; i < 32; i += 8) {
        float v = t[threadIdx.x][threadIdx.y + i];
        __nv_bfloat16 hh, ll; split2(v, hh, ll);
        size_t di = (size_t)(nt + threadIdx.y + i) * K + kt + threadIdx.x;
        dhp[di] = hh; dlp[di] = ll;
    }
}

__global__ void wsplit_qkv_kernel(const float* __restrict__ Wq,
                                  const float* __restrict__ Wk,
                                  const float* __restrict__ Wv,
                                  __nv_bfloat16* __restrict__ dh,
                                  __nv_bfloat16* __restrict__ dl) {
    __shared__ float t[32][33];
    int z = blockIdx.z;
    int layer = z / 3, which = z % 3;
    const float* src = ((which == 0) ? Wq : (which == 1) ? Wk : Wv) + (size_t)layer * D * D;
    int nt = blockIdx.x * 32, kt = blockIdx.y * 32;
    #pragma unroll
    for (int i = 0; i < 32; i += 8)
        t[threadIdx.y + i][threadIdx.x] = src[(size_t)(kt + threadIdx.y + i) * D + nt + threadIdx.x];
    __syncthreads();
    size_t dbase = (size_t)layer * 768 * D + (size_t)which * 256 * D;
    #pragma unroll
    for (int i = 0; i < 32; i += 8) {
        float v = t[threadIdx.x][threadIdx.y + i];
        __nv_bfloat16 hh, ll; split2(v, hh, ll);
        size_t di = dbase + (size_t)(nt + threadIdx.y + i) * D + kt + threadIdx.x;
        dh[di] = hh; dl[di] = ll;
    }
}

// ---------------- LayerNorm core ----------------
__device__ __forceinline__ void ln_row(float4 v0, float4 v1,
                                       const float* gam, const float* bet, int lane,
                                       __nv_bfloat16* oh, __nv_bfloat16* ol, size_t base) {
    float s = v0.x + v0.y + v0.z + v0.w + v1.x + v1.y + v1.z + v1.w;
    #pragma unroll
    for (int o = 16; o > 0; o >>= 1) s += __shfl_xor_sync(0xffffffffu, s, o);
    float mu = s * (1.0f / 256.0f);
    float d0x = v0.x - mu, d0y = v0.y - mu, d0z = v0.z - mu, d0w = v0.w - mu;
    float d1x = v1.x - mu, d1y = v1.y - mu, d1z = v1.z - mu, d1w = v1.w - mu;
    float ss = d0x*d0x + d0y*d0y + d0z*d0z + d0w*d0w
             + d1x*d1x + d1y*d1y + d1z*d1z + d1w*d1w;
    #pragma unroll
    for (int o = 16; o > 0; o >>= 1) ss += __shfl_xor_sync(0xffffffffu, ss, o);
    float inv = rsqrtf(ss * (1.0f / 256.0f) + 1e-6f);
    float4 g0 = ((const float4*)gam)[lane];
    float4 g1 = ((const float4*)gam)[lane + 32];
    float4 b0 = ((const float4*)bet)[lane];
    float4 b1 = ((const float4*)bet)[lane + 32];
    float o00 = d0x * inv * g0.x + b0.x, o01 = d0y * inv * g0.y + b0.y;
    float o02 = d0z * inv * g0.z + b0.z, o03 = d0w * inv * g0.w + b0.w;
    float o10 = d1x * inv * g1.x + b1.x, o11 = d1y * inv * g1.y + b1.y;
    float o12 = d1z * inv * g1.z + b1.z, o13 = d1w * inv * g1.w + b1.w;
    uint32_t h01, l01, h23, l23;
    packsplit(o00, o01, h01, l01); packsplit(o02, o03, h23, l23);
    *(uint2*)(oh + base) = make_uint2(h01, h23);
    *(uint2*)(ol + base) = make_uint2(l01, l23);
    packsplit(o10, o11, h01, l01); packsplit(o12, o13, h23, l23);
    *(uint2*)(oh + base + 128) = make_uint2(h01, h23);
    *(uint2*)(ol + base + 128) = make_uint2(l01, l23);
}

__global__ void ln_kernel(const float* __restrict__ x,
                          const float* __restrict__ gam,
                          const float* __restrict__ bet,
                          __nv_bfloat16* __restrict__ oh,
                          __nv_bfloat16* __restrict__ ol) {
    int warp = threadIdx.x >> 5, lane = threadIdx.x & 31;
    int token = blockIdx.x * 8 + warp;
    const float4* xr = (const float4*)(x + (size_t)token * D);
    float4 v0 = xr[lane];
    float4 v1 = xr[lane + 32];
    ln_row(v0, v1, gam, bet, lane, oh, ol, (size_t)token * D + lane * 4);
}

__global__ void addpos_ln_kernel(const float* __restrict__ xin,
                                 const float* __restrict__ pos,
                                 float* __restrict__ xout,
                                 const float* __restrict__ gam,
                                 const float* __restrict__ bet,
                                 __nv_bfloat16* __restrict__ oh,
                                 __nv_bfloat16* __restrict__ ol) {
    int warp = threadIdx.x >> 5, lane = threadIdx.x & 31;
    int token = blockIdx.x * 8 + warp;
    int l = token % SEQ;
    const float4* xr = (const float4*)(xin + (size_t)token * D);
    const float4* pr = (const float4*)(pos + (size_t)l * D);
    float4 v0 = xr[lane],      p0 = pr[lane];
    float4 v1 = xr[lane + 32], p1 = pr[lane + 32];
    v0.x += p0.x; v0.y += p0.y; v0.z += p0.z; v0.w += p0.w;
    v1.x += p1.x; v1.y += p1.y; v1.z += p1.z; v1.w += p1.w;
    float4* xo = (float4*)(xout + (size_t)token * D);
    xo[lane] = v0; xo[lane + 32] = v1;
    ln_row(v0, v1, gam, bet, lane, oh, ol, (size_t)token * D + lane * 4);
}

// ---------------- HMMA GEMM: 512 threads, warp-tile 32x32 ----------------
#define PITCHB 144
#define MATB   (128 * PITCHB)
#define STAGEB (4 * MATB)
#define GSMEM  (2 * STAGEB)

template<int EPI>
__global__ void __launch_bounds__(512, 1)
tc_gemm(const __nv_bfloat16* __restrict__ Ahi, const __nv_bfloat16* __restrict__ Alo,
        const __nv_bfloat16* __restrict__ Bthi, const __nv_bfloat16* __restrict__ Btlo,
        const float* __restrict__ bias0, const float* __restrict__ bias1,
        const float* __restrict__ bias2,
        float* __restrict__ Co,
        __nv_bfloat16* __restrict__ Chi, __nv_bfloat16* __restrict__ Clo,
        int K, int ldc) {
    extern __shared__ char smem[];
    uint32_t sb = smem_u32(smem);
    int tid = threadIdx.x;
    int wid = tid >> 5, lane = tid & 31;
    int wm = wid & 3, wn = wid >> 2;
    int row0 = blockIdx.y * 128, col0 = blockIdx.x * 128;

    float acc[2][4][4];
    #pragma unroll
    for (int a = 0; a < 2; a++)
        #pragma unroll
        for (int b = 0; b < 4; b++)
            #pragma unroll
            for (int c = 0; c < 4; c++) acc[a][b][c] = 0.0f;

    int arow = lane & 15, acolh = lane >> 4;
    int brow = ((lane >> 4) << 3) + (lane & 7), bkh = (lane >> 3) & 1;

    int nk = K >> 6;

    auto load_chunk = [&](int c) {
        int s = c & 1; int kc = c << 6;
        #pragma unroll
        for (int m = 0; m < 4; m++) {
            const __nv_bfloat16* src = (m == 0) ? Ahi : (m == 1) ? Alo : (m == 2) ? Bthi : Btlo;
            int rbase = (m < 2) ? row0 : col0;
            #pragma unroll
            for (int i = 0; i < 2; i++) {
                int idx = i * 512 + tid;
                int r = idx >> 3, u = idx & 7;
                const void* g = src + (size_t)(rbase + r) * K + kc + u * 8;
                uint32_t dsh = sb + s * STAGEB + m * MATB + r * PITCHB + u * 16;
                cp16(dsh, g);
            }
        }
    };

    load_chunk(0); CP_COMMIT();
    for (int c = 0; c < nk; c++) {
        if (c + 1 < nk) load_chunk(c + 1);
        CP_COMMIT();
        CP_WAIT1();
        __syncthreads();
        uint32_t st = sb + (c & 1) * STAGEB;
        #pragma unroll
        for (int k16 = 0; k16 < 4; k16++) {
            uint32_t ah[2][4], al[2][4], bh[2][4], bl[2][4];
            #pragma unroll
            for (int mf = 0; mf < 2; mf++) {
                uint32_t ro = (uint32_t)(wm * 32 + mf * 16 + arow) * PITCHB + acolh * 16 + k16 * 32;
                ldsm4(ah[mf], st + ro);
                ldsm4(al[mf], st + MATB + ro);
            }
            #pragma unroll
            for (int g = 0; g < 2; g++) {
                uint32_t ro = (uint32_t)(wn * 32 + g * 16 + brow) * PITCHB + bkh * 16 + k16 * 32;
                ldsm4(bh[g], st + 2 * MATB + ro);
                ldsm4(bl[g], st + 3 * MATB + ro);
            }
            #pragma unroll
            for (int mf = 0; mf < 2; mf++)
                #pragma unroll
                for (int nf = 0; nf < 4; nf++)
                    mma_bf16(acc[mf][nf], ah[mf], &bh[nf >> 1][(nf & 1) * 2]);
            #pragma unroll
            for (int mf = 0; mf < 2; mf++)
                #pragma unroll
                for (int nf = 0; nf < 4; nf++)
                    mma_bf16(acc[mf][nf], ah[mf], &bl[nf >> 1][(nf & 1) * 2]);
            #pragma unroll
            for (int mf = 0; mf < 2; mf++)
                #pragma unroll
                for (int nf = 0; nf < 4; nf++)
                    mma_bf16(acc[mf][nf], al[mf], &bh[nf >> 1][(nf & 1) * 2]);
        }
        __syncthreads();
    }

    int qid = lane >> 2, tig = lane & 3;
    #pragma unroll
    for (int mf = 0; mf < 2; mf++) {
        #pragma unroll
        for (int rr = 0; rr < 2; rr++) {
            int grow = row0 + wm * 32 + mf * 16 + rr * 8 + qid;
            #pragma unroll
            for (int nf = 0; nf < 4; nf++) {
                int lcol = wn * 32 + nf * 8 + 2 * tig;
                float va = acc[mf][nf][rr * 2 + 0];
                float vb = acc[mf][nf][rr * 2 + 1];
                if (EPI == 0) {
                    int sel = blockIdx.x >> 1;
                    const float* bp = ((sel == 0) ? bias0 : (sel == 1) ? bias1 : bias2)
                                      + (blockIdx.x & 1) * 128 + lcol;
                    float2 r; r.x = va + bp[0]; r.y = vb + bp[1];
                    *(float2*)(Co + (size_t)grow * ldc + col0 + lcol) = r;
                } else if (EPI == 2) {
                    const float* bp = bias0 + col0 + lcol;
                    float2* cp = (float2*)(Co + (size_t)grow * ldc + col0 + lcol);
                    float2 old = *cp;
                    float2 r; r.x = old.x + va + bp[0]; r.y = old.y + vb + bp[1];
                    *cp = r;
                } else {
                    const float* bp = bias0 + col0 + lcol;
                    float ga = gelu_exact(va + bp[0]);
                    float gb = gelu_exact(vb + bp[1]);
                    uint32_t hp, lp;
                    packsplit(ga, gb, hp, lp);
                    *(uint32_t*)(Chi + (size_t)grow * ldc + col0 + lcol) = hp;
                    *(uint32_t*)(Clo + (size_t)grow * ldc + col0 + lcol) = lp;
                }
            }
        }
    }
}

// ---------------- tensor-core flash attention ----------------
// One block per (b,h). K/V staged in smem as bf16 hi/lo (pitch 80B).
// Each warp: m16 query tiles, online softmax over 7 chunks of 64 keys.
// Scores: Qh*Kh + Qh*Kl + Ql*Kh (fp32-accurate). PV: Ph*Vh + Ph*Vl + Pl*Vh.
#define APITCH 80
#define AK_HI 0
#define AK_LO 35840
#define AV_HI 71680
#define AV_LO 107520
#define AMASK 143360
#define ASMEM 145408

__global__ void __launch_bounds__(256)
attn_kernel(const float* __restrict__ qkv,
            const unsigned char* __restrict__ mask,
            __nv_bfloat16* __restrict__ aoh,
            __nv_bfloat16* __restrict__ aol) {
    extern __shared__ char sm[];
    uint32_t sb = smem_u32(sm);
    int bh = blockIdx.x;
    int b = bh >> 3, h = bh & 7;
    int tid = threadIdx.x, warp = tid >> 5, lane = tid & 31;
    size_t base = (size_t)b * SEQ * 768 + h * 32;

    // stage K/V hi/lo into smem
    for (int idx = tid; idx < SEQ * 8; idx += 256) {
        int j = idx >> 3, d4 = idx & 7;
        const float* rowp = qkv + base + (size_t)j * 768 + d4 * 4;
        float4 kv = *(const float4*)(rowp + 256);
        float4 vv = *(const float4*)(rowp + 512);
        uint32_t off = (uint32_t)j * APITCH + d4 * 8;
        uint32_t h01, l01, h23, l23;
        packsplit(kv.x, kv.y, h01, l01); packsplit(kv.z, kv.w, h23, l23);
        *(uint2*)(sm + AK_HI + off) = make_uint2(h01, h23);
        *(uint2*)(sm + AK_LO + off) = make_uint2(l01, l23);
        packsplit(vv.x, vv.y, h01, l01); packsplit(vv.z, vv.w, h23, l23);
        *(uint2*)(sm + AV_HI + off) = make_uint2(h01, h23);
        *(uint2*)(sm + AV_LO + off) = make_uint2(l01, l23);
    }
    for (int j = tid; j < SEQ; j += 256)
        *(float*)(sm + AMASK + j * 4) = mask[b * SEQ + j] ? 1.0f : 0.0f;
    __syncthreads();

    int r = lane >> 2, c = lane & 3;
    int kb_row  = ((lane >> 4) << 3) + (lane & 7);
    int kb_koff = ((lane >> 3) & 1) * 16;
    int vb_row  = (lane & 7) + ((lane >> 3) & 1) * 8;
    int vb_noff = (lane >> 4) * 16;
    const float scale = 0.17677669529663687f;

    for (int mt = warp; mt < 28; mt += 8) {
        int m0 = mt * 16;
        // Q fragments (hi/lo) straight from gmem fp32
        uint32_t qh[2][4], ql[2][4];
        #pragma unroll
        for (int ks = 0; ks < 2; ks++) {
            int k0 = ks * 16 + 2 * c;
            const float* q0p = qkv + base + (size_t)(m0 + r) * 768;
            const float* q1p = qkv + base + (size_t)(m0 + r + 8) * 768;
            float2 f0 = *(const float2*)(q0p + k0);
            float2 f1 = *(const float2*)(q1p + k0);
            float2 f2 = *(const float2*)(q0p + k0 + 8);
            float2 f3 = *(const float2*)(q1p + k0 + 8);
            packsplit(f0.x, f0.y, qh[ks][0], ql[ks][0]);
            packsplit(f1.x, f1.y, qh[ks][1], ql[ks][1]);
            packsplit(f2.x, f2.y, qh[ks][2], ql[ks][2]);
            packsplit(f3.x, f3.y, qh[ks][3], ql[ks][3]);
        }
        float m_r0 = -1e30f, m_r1 = -1e30f;
        float l_r0 = 0.0f, l_r1 = 0.0f;
        float Of[4][4];
        #pragma unroll
        for (int nt = 0; nt < 4; nt++) {
            Of[nt][0] = 0.f; Of[nt][1] = 0.f; Of[nt][2] = 0.f; Of[nt][3] = 0.f;
        }

        for (int ch = 0; ch < 7; ch++) {
            int nb = ch * 64;
            float sacc[8][4];
            #pragma unroll
            for (int t = 0; t < 8; t++) {
                sacc[t][0] = 0.f; sacc[t][1] = 0.f; sacc[t][2] = 0.f; sacc[t][3] = 0.f;
            }
            #pragma unroll
            for (int ks = 0; ks < 2; ks++) {
                uint32_t kh[4][4], kl[4][4];
                #pragma unroll
                for (int g = 0; g < 4; g++) {
                    uint32_t ro = sb + AK_HI + (uint32_t)(nb + g * 16 + kb_row) * APITCH
                                + kb_koff + ks * 32;
                    ldsm4(kh[g], ro);
                    ldsm4(kl[g], ro + (AK_LO - AK_HI));
                }
                #pragma unroll
                for (int g = 0; g < 4; g++) {
                    mma_bf16(sacc[2*g],   qh[ks], &kh[g][0]);
                    mma_bf16(sacc[2*g+1], qh[ks], &kh[g][2]);
                }
                #pragma unroll
                for (int g = 0; g < 4; g++) {
                    mma_bf16(sacc[2*g],   qh[ks], &kl[g][0]);
                    mma_bf16(sacc[2*g+1], qh[ks], &kl[g][2]);
                }
                #pragma unroll
                for (int g = 0; g < 4; g++) {
                    mma_bf16(sacc[2*g],   ql[ks], &kh[g][0]);
                    mma_bf16(sacc[2*g+1], ql[ks], &kh[g][2]);
                }
            }
            // scale + mask(replace) + row max
            float mx0 = -1e30f, mx1 = -1e30f;
            #pragma unroll
            for (int t = 0; t < 8; t++) {
                int j0 = nb + t * 8 + 2 * c;
                float f0 = *(const float*)(sm + AMASK + j0 * 4);
                float f1 = *(const float*)(sm + AMASK + (j0 + 1) * 4);
                float s0 = sacc[t][0] * scale; s0 = fmaf(f0, -10000.0f - s0, s0);
                float s1 = sacc[t][1] * scale; s1 = fmaf(f1, -10000.0f - s1, s1);
                float s2 = sacc[t][2] * scale; s2 = fmaf(f0, -10000.0f - s2, s2);
                float s3 = sacc[t][3] * scale; s3 = fmaf(f1, -10000.0f - s3, s3);
                sacc[t][0] = s0; sacc[t][1] = s1; sacc[t][2] = s2; sacc[t][3] = s3;
                mx0 = fmaxf(mx0, fmaxf(s0, s1));
                mx1 = fmaxf(mx1, fmaxf(s2, s3));
            }
            mx0 = fmaxf(mx0, __shfl_xor_sync(0xffffffffu, mx0, 1));
            mx0 = fmaxf(mx0, __shfl_xor_sync(0xffffffffu, mx0, 2));
            mx1 = fmaxf(mx1, __shfl_xor_sync(0xffffffffu, mx1, 1));
            mx1 = fmaxf(mx1, __shfl_xor_sync(0xffffffffu, mx1, 2));
            float mn0 = fmaxf(m_r0, mx0), mn1 = fmaxf(m_r1, mx1);
            float co0 = __expf(m_r0 - mn0), co1 = __expf(m_r1 - mn1);
            m_r0 = mn0; m_r1 = mn1;
            float rs0 = 0.0f, rs1 = 0.0f;
            #pragma unroll
            for (int t = 0; t < 8; t++) {
                sacc[t][0] = __expf(sacc[t][0] - mn0);
                sacc[t][1] = __expf(sacc[t][1] - mn0);
                sacc[t][2] = __expf(sacc[t][2] - mn1);
                sacc[t][3] = __expf(sacc[t][3] - mn1);
                rs0 += sacc[t][0] + sacc[t][1];
                rs1 += sacc[t][2] + sacc[t][3];
            }
            rs0 += __shfl_xor_sync(0xffffffffu, rs0, 1);
            rs0 += __shfl_xor_sync(0xffffffffu, rs0, 2);
            rs1 += __shfl_xor_sync(0xffffffffu, rs1, 1);
            rs1 += __shfl_xor_sync(0xffffffffu, rs1, 2);
            l_r0 = l_r0 * co0 + rs0;
            l_r1 = l_r1 * co1 + rs1;
            #pragma unroll
            for (int nt = 0; nt < 4; nt++) {
                Of[nt][0] *= co0; Of[nt][1] *= co0;
                Of[nt][2] *= co1; Of[nt][3] *= co1;
            }
            // pack P fragments (C-frag -> A-frag identity), hi/lo split
            uint32_t pha[4][4], pla[4][4];
            #pragma unroll
            for (int kk = 0; kk < 4; kk++) {
                packsplit(sacc[2*kk][0],   sacc[2*kk][1],   pha[kk][0], pla[kk][0]);
                packsplit(sacc[2*kk][2],   sacc[2*kk][3],   pha[kk][1], pla[kk][1]);
                packsplit(sacc[2*kk+1][0], sacc[2*kk+1][1], pha[kk][2], pla[kk][2]);
                packsplit(sacc[2*kk+1][2], sacc[2*kk+1][3], pha[kk][3], pla[kk][3]);
            }
            // P @ V
            #pragma unroll
            for (int kk = 0; kk < 4; kk++) {
                uint32_t vh0[4], vh1[4], vl0[4], vl1[4];
                uint32_t ro = sb + AV_HI + (uint32_t)(nb + kk * 16 + vb_row) * APITCH + vb_noff;
                ldsm4t(vh0, ro);
                ldsm4t(vh1, ro + 32);
                ldsm4t(vl0, ro + (AV_LO - AV_HI));
                ldsm4t(vl1, ro + (AV_LO - AV_HI) + 32);
                mma_bf16(Of[0], pha[kk], &vh0[0]); mma_bf16(Of[1], pha[kk], &vh0[2]);
                mma_bf16(Of[2], pha[kk], &vh1[0]); mma_bf16(Of[3], pha[kk], &vh1[2]);
                mma_bf16(Of[0], pha[kk], &vl0[0]); mma_bf16(Of[1], pha[kk], &vl0[2]);
                mma_bf16(Of[2], pha[kk], &vl1[0]); mma_bf16(Of[3], pha[kk], &vl1[2]);
                mma_bf16(Of[0], pla[kk], &vh0[0]); mma_bf16(Of[1], pla[kk], &vh0[2]);
                mma_bf16(Of[2], pla[kk], &vh1[0]); mma_bf16(Of[3], pla[kk], &vh1[2]);
            }
        }
        float inv0 = 1.0f / l_r0, inv1 = 1.0f / l_r1;
        size_t tok0 = (size_t)(b * SEQ + m0 + r) * D;
        size_t tok1 = tok0 + 8 * D;
        #pragma unroll
        for (int nt = 0; nt < 4; nt++) {
            int dd = h * 32 + nt * 8 + 2 * c;
            uint32_t hp, lp;
            packsplit(Of[nt][0] * inv0, Of[nt][1] * inv0, hp, lp);
            *(uint32_t*)(aoh + tok0 + dd) = hp;
            *(uint32_t*)(aol + tok0 + dd) = lp;
            packsplit(Of[nt][2] * inv1, Of[nt][3] * inv1, hp, lp);
            *(uint32_t*)(aoh + tok1 + dd) = hp;
            *(uint32_t*)(aol + tok1 + dd) = lp;
        }
    }
}

// ---------------- launch ----------------
extern "C" void kernel_launch(void* const* d_in, const int* in_sizes, int n_in,
                              void* d_out, int out_size) {
    const float* x_in = (const float*)d_in[0];
    const unsigned char* mask = (const unsigned char*)d_in[1];
    const float* pos  = (const float*)d_in[2];
    const float* Wq   = (const float*)d_in[3];
    const float* bq   = (const float*)d_in[4];
    const float* Wk   = (const float*)d_in[5];
    const float* bk   = (const float*)d_in[6];
    const float* Wv   = (const float*)d_in[7];
    const float* bv   = (const float*)d_in[8];
    const float* Wo   = (const float*)d_in[9];
    const float* bo   = (const float*)d_in[10];
    const float* W1   = (const float*)d_in[11];
    const float* bf1  = (const float*)d_in[12];
    const float* W2   = (const float*)d_in[13];
    const float* bf2  = (const float*)d_in[14];
    const float* ln1g = (const float*)d_in[15];
    const float* ln1b = (const float*)d_in[16];
    const float* ln2g = (const float*)d_in[17];
    const float* ln2b = (const float*)d_in[18];
    float* x = (float*)d_out;

    float* qkv;
    __nv_bfloat16 *nxh, *nxl, *aoh, *aol, *hh, *hl;
    __nv_bfloat16 *wqkvh, *wqkvl, *woth, *wotl, *w1th, *w1tl, *w2th, *w2tl;
    cudaGetSymbolAddress((void**)&qkv, g_qkv);
    cudaGetSymbolAddress((void**)&nxh, g_nxh);  cudaGetSymbolAddress((void**)&nxl, g_nxl);
    cudaGetSymbolAddress((void**)&aoh, g_aoh);  cudaGetSymbolAddress((void**)&aol, g_aol);
    cudaGetSymbolAddress((void**)&hh,  g_hh);   cudaGetSymbolAddress((void**)&hl,  g_hl);
    cudaGetSymbolAddress((void**)&wqkvh, g_wqkvh); cudaGetSymbolAddress((void**)&wqkvl, g_wqkvl);
    cudaGetSymbolAddress((void**)&woth,  g_woth);  cudaGetSymbolAddress((void**)&wotl,  g_wotl);
    cudaGetSymbolAddress((void**)&w1th,  g_w1th);  cudaGetSymbolAddress((void**)&w1tl,  g_w1tl);
    cudaGetSymbolAddress((void**)&w2th,  g_w2th);  cudaGetSymbolAddress((void**)&w2tl,  g_w2tl);

    cudaFuncSetAttribute(attn_kernel, cudaFuncAttributeMaxDynamicSharedMemorySize, ASMEM);
    cudaFuncSetAttribute(tc_gemm<0>, cudaFuncAttributeMaxDynamicSharedMemorySize, GSMEM);
    cudaFuncSetAttribute(tc_gemm<1>, cudaFuncAttributeMaxDynamicSharedMemorySize, GSMEM);
    cudaFuncSetAttribute(tc_gemm<2>, cudaFuncAttributeMaxDynamicSharedMemorySize, GSMEM);

    wsplit_qkv_kernel<<<dim3(8, 8, 3 * NLAYERS), dim3(32, 8)>>>(Wq, Wk, Wv, wqkvh, wqkvl);
    wsplit_kernel<<<dim3(8, 8, NLAYERS),  dim3(32, 8)>>>(Wo, woth, wotl, D, D, D * D);
    wsplit_kernel<<<dim3(32, 8, NLAYERS), dim3(32, 8)>>>(W1, w1th, w1tl, D, FFD, (size_t)FFD * D);
    wsplit_kernel<<<dim3(8, 32, NLAYERS), dim3(32, 8)>>>(W2, w2th, w2tl, FFD, D, (size_t)D * FFD);

    for (int l = 0; l < NLAYERS; l++) {
        if (l == 0) {
            addpos_ln_kernel<<<NTOK / 8, 256>>>(x_in, pos, x, ln1g, ln1b, nxh, nxl);
        } else {
            ln_kernel<<<NTOK / 8, 256>>>(x, ln1g + l * D, ln1b + l * D, nxh, nxl);
        }

        tc_gemm<0><<<dim3(6, 112), 512, GSMEM>>>(
            nxh, nxl, wqkvh + (size_t)l * 768 * D, wqkvl + (size_t)l * 768 * D,
            bq + l * D, bk + l * D, bv + l * D,
            qkv, nullptr, nullptr, D, 768);

        attn_kernel<<<BATCH * H, 256, ASMEM>>>(qkv, mask, aoh, aol);

        tc_gemm<2><<<dim3(2, 112), 512, GSMEM>>>(
            aoh, aol, woth + (size_t)l * D * D, wotl + (size_t)l * D * D,
            bo + l * D, nullptr, nullptr,
            x, nullptr, nullptr, D, D);

        ln_kernel<<<NTOK / 8, 256>>>(x, ln2g + l * D, ln2b + l * D, nxh, nxl);

        tc_gemm<1><<<dim3(8, 112), 512, GSMEM>>>(
            nxh, nxl, w1th + (size_t)l * FFD * D, w1tl + (size_t)l * FFD * D,
            bf1 + l * FFD, nullptr, nullptr,
            nullptr, hh, hl, D, FFD);

        tc_gemm<2><<<dim3(2, 112), 512, GSMEM>>>(
            hh, hl, w2th + (size_t)l * D * FFD, w2tl + (size_t)l * D * FFD,
            bf2 + l * D, nullptr, nullptr,
            x, nullptr, nullptr, FFD, D);
    }
}